// round 9
// baseline (speedup 1.0000x reference)
#include <cuda_runtime.h>
#include <cstdint>

// Problem constants
#define B   16
#define NC  31
#define NO  3
#define NX  256
#define NY  256
#define NLOC 7533          // 3*31*81
#define NGRP 93            // 3*31
#define WROW 10            // padded weight row (9 taps + 1 pad) for 16B align
#define WCH  90            // WROW * 9 dy rows per (o,c)

// Tiling
#define TILE_H 32
#define TILE_W 128
#define THR    256         // 16 thread-rows x 16 thread-cols
#define TH     2           // output rows per thread
#define HALF   64          // lane split: f32x2 lanes are cols (w, w+64)
#define SROWS  40          // TILE_H + 8 halo
#define SP2    72          // float2 pairs per smem row = 36 16B chunks

__device__ float2 g_w2[NO * NC * WCH]; // relu'd weights, duplicated lanes, padded rows
__device__ int    g_off[NGRP];         // per (o,c) column offset cx-8 in [-4,4]

__device__ __forceinline__ void fma2(unsigned long long& acc,
                                     unsigned long long a,
                                     unsigned long long b) {
    asm("fma.rn.f32x2 %0, %1, %2, %0;" : "+l"(acc) : "l"(a), "l"(b));
}
__device__ __forceinline__ void unpk2(unsigned long long v, float& lo, float& hi) {
    asm("mov.b64 {%0, %1}, %2;" : "=f"(lo), "=f"(hi) : "l"(v));
}

// chunk swizzle: break the 32B-stride / 128B-period 4-way conflict
__device__ __host__ __forceinline__ int swz(int c) {
    return c ^ ((c >> 3) & 1);
}

// ---- prep: relu + duplicate weights into padded rows, extract offsets ----
__global__ void prep_kernel(const float* __restrict__ vk,
                            const int* __restrict__ loc) {
    int t = blockIdx.x * blockDim.x + threadIdx.x;
    if (t < NLOC) {
        int g   = t / 81;
        int rem = t - g * 81;
        int dyi = rem / 9;
        int dx  = rem - dyi * 9;
        float w = fmaxf(vk[t], 0.0f);
        g_w2[g * WCH + dyi * WROW + dx] = make_float2(w, w);
    }
    if (t < NGRP) {
        int loc0 = loc[t * 81];          // first entry: (dy=-4, dx=-4)
        g_off[t] = (loc0 % 17) - 4;      // cx - 8
    }
}

// ---- main conv: one block = (b, o, 32x128 tile), 256 threads ----
__global__ __launch_bounds__(THR)
void conv_kernel(const float* __restrict__ x, float* __restrict__ out) {
    __shared__ __align__(16) float2 s2[SROWS * SP2]; // swizzled interleaved pairs
    __shared__ __align__(16) float2 ws[WCH];         // channel weights, padded rows

    const int bz = blockIdx.z;
    const int b  = bz / NO;
    const int o  = bz % NO;
    const int y0 = blockIdx.y * TILE_H;
    const int x0 = blockIdx.x * TILE_W;

    const int tid = threadIdx.x;
    const int twi = tid & 15;        // 0..15
    const int thi = tid >> 4;        // 0..15
    const int h0  = thi * TH;        // tile-local out row base (0..30)
    const int w0p = twi * 4;         // logical pair base (chunk base = twi*2)

    // per-thread swizzled chunk byte-offsets within a row (6 chunks)
    int coff[6];
    #pragma unroll
    for (int k = 0; k < 6; k++)
        coff[k] = swz(twi * 2 + k) * 16;

    unsigned long long acc[TH][4];
    #pragma unroll
    for (int i = 0; i < TH; i++)
        #pragma unroll
        for (int j = 0; j < 4; j++) acc[i][j] = 0ULL;

    for (int c = 0; c < NC; c++) {
        const int oc = g_off[o * NC + c];
        const float* __restrict__ xc = x + ((size_t)(b * NC + c)) * (NX * NY);
        const int gx0 = x0 - 4 + oc;

        // stage weights (padded, duplicated pairs) into smem
        if (tid < WCH)
            ws[tid] = __ldg(&g_w2[(o * NC + c) * WCH + tid]);

        // stage channel tile into smem: pair p of row -> swizzled chunk pos
        #pragma unroll 4
        for (int i = tid; i < SROWS * SP2; i += THR) {
            int row = i / SP2;
            int p   = i - row * SP2;
            int gy  = y0 + row - 4;
            int gxa = gx0 + p;
            int gxb = gxa + HALF;
            float va = 0.0f, vb = 0.0f;
            if ((unsigned)gy < (unsigned)NX) {
                const float* rowp = xc + gy * NY;
                if ((unsigned)gxa < (unsigned)NY) va = __ldg(rowp + gxa);
                if ((unsigned)gxb < (unsigned)NY) vb = __ldg(rowp + gxb);
            }
            int pos = row * SP2 + swz(p >> 1) * 2 + (p & 1);
            s2[pos] = make_float2(va, vb);
        }
        __syncthreads();

        #pragma unroll
        for (int r = 0; r < TH + 8; r++) {       // 10 input rows
            const char* rb = (const char*)&s2[(h0 + r) * SP2];
            unsigned long long q[12];
            #pragma unroll
            for (int k = 0; k < 6; k++) {
                ulonglong2 u = *(const ulonglong2*)(rb + coff[k]);
                q[2 * k]     = u.x;
                q[2 * k + 1] = u.y;
            }

            #pragma unroll
            for (int hh = 0; hh < TH; hh++) {
                const int dyi = r - hh;          // dy + 4
                if (dyi < 0 || dyi > 8) continue;
                const ulonglong2* __restrict__ w2 =
                    (const ulonglong2*)(ws + dyi * WROW);
                ulonglong2 wab = w2[0];          // taps 0,1
                ulonglong2 wcd = w2[1];          // taps 2,3
                ulonglong2 wef = w2[2];          // taps 4,5
                ulonglong2 wgh = w2[3];          // taps 6,7
                unsigned long long w8 =
                    *(const unsigned long long*)(ws + dyi * WROW + 8);

                fma2(acc[hh][0], wab.x, q[0]);
                fma2(acc[hh][1], wab.x, q[1]);
                fma2(acc[hh][2], wab.x, q[2]);
                fma2(acc[hh][3], wab.x, q[3]);
                fma2(acc[hh][0], wab.y, q[1]);
                fma2(acc[hh][1], wab.y, q[2]);
                fma2(acc[hh][2], wab.y, q[3]);
                fma2(acc[hh][3], wab.y, q[4]);
                fma2(acc[hh][0], wcd.x, q[2]);
                fma2(acc[hh][1], wcd.x, q[3]);
                fma2(acc[hh][2], wcd.x, q[4]);
                fma2(acc[hh][3], wcd.x, q[5]);
                fma2(acc[hh][0], wcd.y, q[3]);
                fma2(acc[hh][1], wcd.y, q[4]);
                fma2(acc[hh][2], wcd.y, q[5]);
                fma2(acc[hh][3], wcd.y, q[6]);
                fma2(acc[hh][0], wef.x, q[4]);
                fma2(acc[hh][1], wef.x, q[5]);
                fma2(acc[hh][2], wef.x, q[6]);
                fma2(acc[hh][3], wef.x, q[7]);
                fma2(acc[hh][0], wef.y, q[5]);
                fma2(acc[hh][1], wef.y, q[6]);
                fma2(acc[hh][2], wef.y, q[7]);
                fma2(acc[hh][3], wef.y, q[8]);
                fma2(acc[hh][0], wgh.x, q[6]);
                fma2(acc[hh][1], wgh.x, q[7]);
                fma2(acc[hh][2], wgh.x, q[8]);
                fma2(acc[hh][3], wgh.x, q[9]);
                fma2(acc[hh][0], wgh.y, q[7]);
                fma2(acc[hh][1], wgh.y, q[8]);
                fma2(acc[hh][2], wgh.y, q[9]);
                fma2(acc[hh][3], wgh.y, q[10]);
                fma2(acc[hh][0], w8, q[8]);
                fma2(acc[hh][1], w8, q[9]);
                fma2(acc[hh][2], w8, q[10]);
                fma2(acc[hh][3], w8, q[11]);
            }
        }
        __syncthreads();
    }

    // write: lane0 -> cols x0+w0.., lane1 -> cols x0+64+w0..
    float* __restrict__ op =
        out + (((size_t)(b * NO + o)) * NX + (y0 + h0)) * NY + x0 + w0p;
    #pragma unroll
    for (int hh = 0; hh < TH; hh++) {
        float a0, b0, a1, b1, a2, b2, a3, b3;
        unpk2(acc[hh][0], a0, b0);
        unpk2(acc[hh][1], a1, b1);
        unpk2(acc[hh][2], a2, b2);
        unpk2(acc[hh][3], a3, b3);
        *(float4*)(op + hh * NY)        = make_float4(a0, a1, a2, a3);
        *(float4*)(op + hh * NY + HALF) = make_float4(b0, b1, b2, b3);
    }
}

extern "C" void kernel_launch(void* const* d_in, const int* in_sizes, int n_in,
                              void* d_out, int out_size) {
    const float* x   = (const float*)d_in[0];
    const float* vk  = (const float*)d_in[1];
    const int*   loc = (const int*)d_in[2];
    float* out = (float*)d_out;

    prep_kernel<<<30, 256>>>(vk, loc);

    dim3 grid(NY / TILE_W, NX / TILE_H, B * NO);   // (2, 8, 48)
    conv_kernel<<<grid, THR>>>(x, out);
}

// round 10
// speedup vs baseline: 1.0890x; 1.0890x over previous
#include <cuda_runtime.h>
#include <cstdint>

// Problem constants
#define B   16
#define NC  31
#define NO  3
#define NX  256
#define NY  256
#define NLOC 7533          // 3*31*81
#define NGRP 93            // 3*31

// Tiling
#define TILE_H 16
#define TILE_W 128
#define THR    128         // 8 thread-rows x 16 thread-cols
#define TH     2           // output rows per thread
#define HALF   64          // lane split: f32x2 lanes are cols (w, w+64)
#define SROWS  24          // TILE_H + 8 halo
#define SP2    72          // float2 pairs per smem row = 36 16B chunks

__device__ float2 g_w2[NLOC];  // relu'd weights duplicated into both lanes
__device__ int    g_off[NGRP]; // per (o,c) column offset cx-8 in [-4,4]

__device__ __forceinline__ void fma2(unsigned long long& acc,
                                     unsigned long long a,
                                     unsigned long long b) {
    asm("fma.rn.f32x2 %0, %1, %2, %0;" : "+l"(acc) : "l"(a), "l"(b));
}
__device__ __forceinline__ void unpk2(unsigned long long v, float& lo, float& hi) {
    asm("mov.b64 {%0, %1}, %2;" : "=f"(lo), "=f"(hi) : "l"(v));
}

// chunk swizzle: break the 32B-stride / 128B-period 4-way conflict
__device__ __host__ __forceinline__ int swz(int c) {
    return c ^ ((c >> 3) & 1);
}

// ---- prep: relu + duplicate weights, extract per-group column offsets ----
__global__ void prep_kernel(const float* __restrict__ vk,
                            const int* __restrict__ loc) {
    int t = blockIdx.x * blockDim.x + threadIdx.x;
    if (t < NLOC) {
        float w = fmaxf(vk[t], 0.0f);
        g_w2[t] = make_float2(w, w);
    }
    if (t < NGRP) {
        int loc0 = loc[t * 81];          // first entry: (dy=-4, dx=-4)
        g_off[t] = (loc0 % 17) - 4;      // cx - 8
    }
}

// ---- main conv: one block = (b, o, 16x128 tile), 128 threads ----
__global__ __launch_bounds__(THR)
void conv_kernel(const float* __restrict__ x, float* __restrict__ out) {
    __shared__ __align__(16) float2 s2[SROWS * SP2]; // swizzled interleaved pairs
    __shared__ __align__(16) float2 ws[81];          // channel weights, dup lanes

    const int bz = blockIdx.z;
    const int b  = bz / NO;
    const int o  = bz % NO;
    const int y0 = blockIdx.y * TILE_H;
    const int x0 = blockIdx.x * TILE_W;

    const int tid = threadIdx.x;
    const int twi = tid & 15;        // 0..15
    const int thi = tid >> 4;        // 0..7
    const int h0  = thi * TH;        // tile-local out row base (0..14)
    const int w0p = twi * 4;         // logical pair base (chunk base = twi*2)

    // per-thread swizzled chunk byte-offsets within a row (6 chunks)
    int coff[6];
    #pragma unroll
    for (int k = 0; k < 6; k++)
        coff[k] = swz(twi * 2 + k) * 16;

    unsigned long long acc[TH][4];
    #pragma unroll
    for (int i = 0; i < TH; i++)
        #pragma unroll
        for (int j = 0; j < 4; j++) acc[i][j] = 0ULL;

    for (int c = 0; c < NC; c++) {
        const int oc = g_off[o * NC + c];
        const float* __restrict__ xc = x + ((size_t)(b * NC + c)) * (NX * NY);
        const int gx0 = x0 - 4 + oc;

        // stage weights (duplicated pairs) into smem
        if (tid < 81)
            ws[tid] = __ldg(&g_w2[(o * NC + c) * 81 + tid]);

        // stage channel tile into smem: pair p of row -> swizzled chunk pos
        #pragma unroll 4
        for (int i = tid; i < SROWS * SP2; i += THR) {
            int row = i / SP2;
            int p   = i - row * SP2;
            int gy  = y0 + row - 4;
            int gxa = gx0 + p;
            int gxb = gxa + HALF;
            float va = 0.0f, vb = 0.0f;
            if ((unsigned)gy < (unsigned)NX) {
                const float* rowp = xc + gy * NY;
                if ((unsigned)gxa < (unsigned)NY) va = __ldg(rowp + gxa);
                if ((unsigned)gxb < (unsigned)NY) vb = __ldg(rowp + gxb);
            }
            int pos = row * SP2 + swz(p >> 1) * 2 + (p & 1);
            s2[pos] = make_float2(va, vb);
        }
        __syncthreads();

        const unsigned long long* __restrict__ wsu =
            (const unsigned long long*)ws;

        #pragma unroll
        for (int r = 0; r < TH + 8; r++) {       // 10 input rows
            const char* rb = (const char*)&s2[(h0 + r) * SP2];
            unsigned long long q[12];
            #pragma unroll
            for (int k = 0; k < 6; k++) {
                ulonglong2 u = *(const ulonglong2*)(rb + coff[k]);
                q[2 * k]     = u.x;
                q[2 * k + 1] = u.y;
            }

            #pragma unroll
            for (int hh = 0; hh < TH; hh++) {
                const int dyi = r - hh;          // dy + 4
                if (dyi < 0 || dyi > 8) continue;
                const unsigned long long* __restrict__ wr = wsu + dyi * 9;
                #pragma unroll
                for (int dx = 0; dx < 9; dx++) {
                    unsigned long long wp = wr[dx];   // LDS.64 broadcast
                    fma2(acc[hh][0], wp, q[dx + 0]);
                    fma2(acc[hh][1], wp, q[dx + 1]);
                    fma2(acc[hh][2], wp, q[dx + 2]);
                    fma2(acc[hh][3], wp, q[dx + 3]);
                }
            }
        }
        __syncthreads();
    }

    // write: lane0 -> cols x0+w0.., lane1 -> cols x0+64+w0..
    float* __restrict__ op =
        out + (((size_t)(b * NO + o)) * NX + (y0 + h0)) * NY + x0 + w0p;
    #pragma unroll
    for (int hh = 0; hh < TH; hh++) {
        float a0, b0, a1, b1, a2, b2, a3, b3;
        unpk2(acc[hh][0], a0, b0);
        unpk2(acc[hh][1], a1, b1);
        unpk2(acc[hh][2], a2, b2);
        unpk2(acc[hh][3], a3, b3);
        *(float4*)(op + hh * NY)        = make_float4(a0, a1, a2, a3);
        *(float4*)(op + hh * NY + HALF) = make_float4(b0, b1, b2, b3);
    }
}

extern "C" void kernel_launch(void* const* d_in, const int* in_sizes, int n_in,
                              void* d_out, int out_size) {
    const float* x   = (const float*)d_in[0];
    const float* vk  = (const float*)d_in[1];
    const int*   loc = (const int*)d_in[2];
    float* out = (float*)d_out;

    prep_kernel<<<30, 256>>>(vk, loc);

    dim3 grid(NY / TILE_W, NX / TILE_H, B * NO);   // (2, 16, 48)
    conv_kernel<<<grid, THR>>>(x, out);
}